// round 2
// baseline (speedup 1.0000x reference)
#include <cuda_runtime.h>
#include <cstdint>

// ---------------------------------------------------------------------------
// PointNet++ decoder: 3 FP modules, each = {3-NN interp + concat skip} ->
// conv1x1+BN+ReLU -> conv1x1+BN+ReLU.
// Scratch layout: X is (C_rows, B*N cols) row-major so convs are single GEMMs
// and BN stats are per-row reductions.
// ---------------------------------------------------------------------------

#define B_SZ 8
// level sizes
#define N0 8192
#define N1 2048
#define N2 512
#define N3 128

// scratch buffers (device globals: allocation-free scratch).
// Aliasing to reduce static image size:
//   g_big:   X0 (192 x 65536) during FP0 concat/conv0; then reused as Y01.
//   g_mid:   X2 (768 x 4096) during FP2; then reused as Y10 (256 x 16384).
__device__ float g_big[192 * (B_SZ * N0)];   // 50.3 MB
__device__ float g_Y00[128 * (B_SZ * N0)];   // 33.6 MB
__device__ float g_mid[768 * (B_SZ * N2)];   // 12.6 MB (= 192*16384 floats)
__device__ float g_Y20[256 * (B_SZ * N2)];   // 4.2 MB
__device__ float g_F2N[256 * (B_SZ * N2)];   // 4.2 MB
__device__ float g_X1[384 * (B_SZ * N1)];    // 25.2 MB
__device__ float g_F1N[128 * (B_SZ * N1)];   // 8.4 MB
__device__ float g_stats[2 * 256];           // per-channel {mean, rstd}

// ---------------------------------------------------------------------------
// copy skip features (B,C,N) -> X rows [0,C), layout (C, B*N)
// ---------------------------------------------------------------------------
__global__ void copy_skip_kernel(const float* __restrict__ src,
                                 float* __restrict__ dst,
                                 int B, int C, int N) {
    // dst-linear index, vectorized by 4; totals are multiples of 1024
    size_t t = ((size_t)blockIdx.x * blockDim.x + threadIdx.x) * 4;
    int BN = B * N;
    int c = (int)(t / BN);
    int rem = (int)(t % BN);
    int b = rem / N;
    int n = rem % N;
    *(float4*)(dst + t) =
        *(const float4*)(src + ((size_t)b * C + c) * N + n);
}

// ---------------------------------------------------------------------------
// kNN(3) + inverse-distance interpolation.
// feats indexed as feats[b*fb + c*fc + j]; writes X rows [c0, c0+C)
// with column index b*n + pi (row stride = B*n).
// ---------------------------------------------------------------------------
__global__ void knn_interp_kernel(const float* __restrict__ uxyz,  // (B,n,3)
                                  const float* __restrict__ kxyz,  // (B,m,3)
                                  const float* __restrict__ feats,
                                  float* __restrict__ X,
                                  int n, int m, int C, int c0,
                                  int fb, int fc, int B) {
    __shared__ float skx[2048];
    __shared__ float sky[2048];
    __shared__ float skz[2048];

    const int b = blockIdx.y;
    const int pi = blockIdx.x * blockDim.x + threadIdx.x;

    for (int j = threadIdx.x; j < m; j += blockDim.x) {
        const float* p = kxyz + ((size_t)b * m + j) * 3;
        skx[j] = p[0];
        sky[j] = p[1];
        skz[j] = p[2];
    }
    __syncthreads();
    if (pi >= n) return;

    const float* up = uxyz + ((size_t)b * n + pi) * 3;
    const float ux = up[0], uy = up[1], uz = up[2];

    float d0 = 1e30f, d1 = 1e30f, d2 = 1e30f;
    int i0 = 0, i1 = 0, i2 = 0;
    for (int j = 0; j < m; ++j) {
        float dx = ux - skx[j];
        float dy = uy - sky[j];
        float dz = uz - skz[j];
        float d = dx * dx + dy * dy + dz * dz;
        if (d < d2) {
            if (d < d1) {
                d2 = d1; i2 = i1;
                if (d < d0) { d1 = d0; i1 = i0; d0 = d; i0 = j; }
                else        { d1 = d;  i1 = j; }
            } else {
                d2 = d; i2 = j;
            }
        }
    }

    float r0 = 1.0f / (d0 + 1e-8f);
    float r1 = 1.0f / (d1 + 1e-8f);
    float r2 = 1.0f / (d2 + 1e-8f);
    float rs = 1.0f / (r0 + r1 + r2);
    const float w0 = r0 * rs, w1 = r1 * rs, w2 = r2 * rs;

    const float* fbase = feats + (size_t)b * fb;
    const size_t ocol = (size_t)b * n + pi;
    const size_t rowstride = (size_t)B * n;
    float* outp = X + (size_t)c0 * rowstride + ocol;
    for (int c = 0; c < C; ++c) {
        const float* fr = fbase + (size_t)c * fc;
        outp[(size_t)c * rowstride] = w0 * fr[i0] + w1 * fr[i1] + w2 * fr[i2];
    }
}

// ---------------------------------------------------------------------------
// SGEMM: C(M x N) = A(M x K) @ B(K x N), all row-major fp32.
// BM=BN=64, BK=16, 256 threads, 4x4 micro-tile. All dims are exact multiples.
// ---------------------------------------------------------------------------
__global__ __launch_bounds__(256) void sgemm64_kernel(
    const float* __restrict__ A, const float* __restrict__ B,
    float* __restrict__ C, int M, int N, int K) {
    __shared__ float As[16][64];
    __shared__ float Bs[16][64];

    const int tid = threadIdx.x;
    const int bm = blockIdx.y * 64;
    const int bn = blockIdx.x * 64;
    const int tx = tid & 15;   // 0..15 along N
    const int ty = tid >> 4;   // 0..15 along M
    const int arow = tid >> 2;         // 0..63
    const int acol = (tid & 3) << 2;   // 0,4,8,12
    const int brow = tid >> 4;         // 0..15
    const int bcol = (tid & 15) << 2;  // 0..60

    const float* Aptr = A + (size_t)(bm + arow) * K + acol;
    const float* Bptr = B + (size_t)brow * N + bn + bcol;

    float acc[4][4];
#pragma unroll
    for (int i = 0; i < 4; ++i)
#pragma unroll
        for (int j = 0; j < 4; ++j) acc[i][j] = 0.0f;

    for (int k0 = 0; k0 < K; k0 += 16) {
        float4 a4 = *(const float4*)(Aptr + k0);
        float4 b4 = *(const float4*)(Bptr + (size_t)k0 * N);
        As[acol + 0][arow] = a4.x;
        As[acol + 1][arow] = a4.y;
        As[acol + 2][arow] = a4.z;
        As[acol + 3][arow] = a4.w;
        *(float4*)&Bs[brow][bcol] = b4;
        __syncthreads();
#pragma unroll
        for (int kk = 0; kk < 16; ++kk) {
            float4 av = *(const float4*)&As[kk][ty << 2];
            float4 bv = *(const float4*)&Bs[kk][tx << 2];
            acc[0][0] += av.x * bv.x; acc[0][1] += av.x * bv.y;
            acc[0][2] += av.x * bv.z; acc[0][3] += av.x * bv.w;
            acc[1][0] += av.y * bv.x; acc[1][1] += av.y * bv.y;
            acc[1][2] += av.y * bv.z; acc[1][3] += av.y * bv.w;
            acc[2][0] += av.z * bv.x; acc[2][1] += av.z * bv.y;
            acc[2][2] += av.z * bv.z; acc[2][3] += av.z * bv.w;
            acc[3][0] += av.w * bv.x; acc[3][1] += av.w * bv.y;
            acc[3][2] += av.w * bv.z; acc[3][3] += av.w * bv.w;
        }
        __syncthreads();
    }

#pragma unroll
    for (int i = 0; i < 4; ++i) {
        float4 v = make_float4(acc[i][0], acc[i][1], acc[i][2], acc[i][3]);
        *(float4*)(C + (size_t)(bm + (ty << 2) + i) * N + bn + (tx << 2)) = v;
    }
}

// ---------------------------------------------------------------------------
// BN batch stats: per row (channel) of Y (C x Ncols): mean & rsqrt(var+eps)
// ---------------------------------------------------------------------------
__global__ void bn_stats_kernel(const float* __restrict__ Y,
                                float* __restrict__ stats, int Ncols) {
    const int c = blockIdx.x;
    const float* row = Y + (size_t)c * Ncols;
    float s = 0.0f, s2 = 0.0f;
    for (int i = threadIdx.x * 4; i < Ncols; i += blockDim.x * 4) {
        float4 v = *(const float4*)(row + i);
        s += v.x + v.y + v.z + v.w;
        s2 += v.x * v.x + v.y * v.y + v.z * v.z + v.w * v.w;
    }
#pragma unroll
    for (int o = 16; o; o >>= 1) {
        s += __shfl_down_sync(0xFFFFFFFFu, s, o);
        s2 += __shfl_down_sync(0xFFFFFFFFu, s2, o);
    }
    __shared__ float ws[8], ws2[8];
    const int w = threadIdx.x >> 5, l = threadIdx.x & 31;
    if (l == 0) { ws[w] = s; ws2[w] = s2; }
    __syncthreads();
    if (threadIdx.x == 0) {
        float S = 0.0f, S2 = 0.0f;
        const int nw = blockDim.x >> 5;
        for (int i = 0; i < nw; ++i) { S += ws[i]; S2 += ws2[i]; }
        const float inv = 1.0f / (float)Ncols;
        const float mean = S * inv;
        const float var = S2 * inv - mean * mean;
        stats[2 * c] = mean;
        stats[2 * c + 1] = rsqrtf(var + 1e-5f);
    }
}

// ---------------------------------------------------------------------------
// BN apply + ReLU, in place on (C x Ncols)
// ---------------------------------------------------------------------------
__global__ void bn_apply_ip_kernel(float* __restrict__ Y,
                                   const float* __restrict__ stats,
                                   const float* __restrict__ gamma,
                                   const float* __restrict__ beta,
                                   int Ncols) {
    size_t t = ((size_t)blockIdx.x * blockDim.x + threadIdx.x) * 4;
    const int c = (int)(t / Ncols);
    const float g = gamma[c] * stats[2 * c + 1];
    const float b = beta[c] - stats[2 * c] * g;
    float4 v = *(float4*)(Y + t);
    v.x = fmaxf(v.x * g + b, 0.0f);
    v.y = fmaxf(v.y * g + b, 0.0f);
    v.z = fmaxf(v.z * g + b, 0.0f);
    v.w = fmaxf(v.w * g + b, 0.0f);
    *(float4*)(Y + t) = v;
}

// ---------------------------------------------------------------------------
// BN apply + ReLU, (C, B*N) -> out (B,C,N)
// ---------------------------------------------------------------------------
__global__ void bn_apply_out_kernel(const float* __restrict__ Y,
                                    const float* __restrict__ stats,
                                    const float* __restrict__ gamma,
                                    const float* __restrict__ beta,
                                    float* __restrict__ out,
                                    int B, int C, int N) {
    size_t t = ((size_t)blockIdx.x * blockDim.x + threadIdx.x) * 4;
    const int BN = B * N;
    const int c = (int)(t / BN);
    const int rem = (int)(t % BN);
    const int b = rem / N;
    const int n = rem % N;
    const float g = gamma[c] * stats[2 * c + 1];
    const float bb = beta[c] - stats[2 * c] * g;
    float4 v = *(const float4*)(Y + t);
    v.x = fmaxf(v.x * g + bb, 0.0f);
    v.y = fmaxf(v.y * g + bb, 0.0f);
    v.z = fmaxf(v.z * g + bb, 0.0f);
    v.w = fmaxf(v.w * g + bb, 0.0f);
    *(float4*)(out + ((size_t)b * C + c) * N + n) = v;
}

// ---------------------------------------------------------------------------
// host driver
// ---------------------------------------------------------------------------
static inline void run_conv_bn_relu(const float* W, const float* X, float* Y,
                                    float* stats,
                                    const float* gamma, const float* beta,
                                    int M, int Ncols, int K, bool apply_ip) {
    dim3 ggrid(Ncols / 64, M / 64);
    sgemm64_kernel<<<ggrid, 256>>>(W, X, Y, M, Ncols, K);
    bn_stats_kernel<<<M, 256>>>(Y, stats, Ncols);
    if (apply_ip) {
        int total = M * Ncols;
        bn_apply_ip_kernel<<<total / 1024, 256>>>(Y, stats, gamma, beta, Ncols);
    }
}

extern "C" void kernel_launch(void* const* d_in, const int* in_sizes, int n_in,
                              void* d_out, int out_size) {
    const float* in[26];
    for (int i = 0; i < 26 && i < n_in; ++i) in[i] = (const float*)d_in[i];

    // Resolve input ordering: interleaved (setup_inputs dict) vs grouped
    // (reference signature). f0 has 4,194,304 elements; xyz1 has 49,152.
    const float *xyz0, *xyz1, *xyz2, *xyz3, *f0, *f1, *f2, *f3;
    if (in_sizes[1] == 8 * 64 * 8192) {  // interleaved: xyz0,f0,xyz1,f1,...
        xyz0 = in[0]; f0 = in[1]; xyz1 = in[2]; f1 = in[3];
        xyz2 = in[4]; f2 = in[5]; xyz3 = in[6]; f3 = in[7];
    } else {  // grouped: xyz0..xyz3, f0..f3
        xyz0 = in[0]; xyz1 = in[1]; xyz2 = in[2]; xyz3 = in[3];
        f0 = in[4]; f1 = in[5]; f2 = in[6]; f3 = in[7];
    }
    const float *w00 = in[8],  *g00 = in[9],  *b00 = in[10];
    const float *w01 = in[11], *g01 = in[12], *b01 = in[13];
    const float *w10 = in[14], *g10 = in[15], *b10 = in[16];
    const float *w11 = in[17], *g11 = in[18], *b11 = in[19];
    const float *w20 = in[20], *g20 = in[21], *b20 = in[22];
    const float *w21 = in[23], *g21 = in[24], *b21 = in[25];

    float *big, *Y00, *mid, *Y20, *F2N, *X1, *F1N, *stats;
    cudaGetSymbolAddress((void**)&big, g_big);
    cudaGetSymbolAddress((void**)&Y00, g_Y00);
    cudaGetSymbolAddress((void**)&mid, g_mid);
    cudaGetSymbolAddress((void**)&Y20, g_Y20);
    cudaGetSymbolAddress((void**)&F2N, g_F2N);
    cudaGetSymbolAddress((void**)&X1, g_X1);
    cudaGetSymbolAddress((void**)&F1N, g_F1N);
    cudaGetSymbolAddress((void**)&stats, g_stats);

    // Aliased views (see buffer comments above):
    float* X2  = mid;   // 768 x 4096 during FP2
    float* Y10 = mid;   // 256 x 16384 during FP1 (X2 dead by then)
    float* X0  = big;   // 192 x 65536 during FP0 concat + conv0
    float* Y01 = big;   // 128 x 65536 after conv0 (X0 dead as GEMM input? no —
                        // X0 is read by conv0 GEMM, Y01 written by conv1 GEMM
                        // which reads Y00 only; X0 is dead at that point)

    float* out = (float*)d_out;
    const int B = B_SZ;

    // ---------------- FP2: xyz2 (n=512) <- xyz3 (m=128) ----------------
    {
        const int n = N2, m = N3, Cskip = 256, Cf = 512, cols = B * n;
        copy_skip_kernel<<<(B * Cskip * n) / 1024, 256>>>(f2, X2, B, Cskip, n);
        knn_interp_kernel<<<dim3(n / 256, B), 256>>>(
            xyz2, xyz3, f3, X2, n, m, Cf, Cskip, /*fb=*/Cf * m, /*fc=*/m, B);
        run_conv_bn_relu(w20, X2, Y20, stats, g20, b20, 256, cols, 768, true);
        run_conv_bn_relu(w21, Y20, F2N, stats, g21, b21, 256, cols, 256, true);
    }

    // ---------------- FP1: xyz1 (n=2048) <- xyz2 (m=512) ----------------
    {
        const int n = N1, m = N2, Cskip = 128, Cf = 256, cols = B * n;
        copy_skip_kernel<<<(B * Cskip * n) / 1024, 256>>>(f1, X1, B, Cskip, n);
        knn_interp_kernel<<<dim3(n / 256, B), 256>>>(
            xyz1, xyz2, F2N, X1, n, m, Cf, Cskip, /*fb=*/m, /*fc=*/B * m, B);
        run_conv_bn_relu(w10, X1, Y10, stats, g10, b10, 256, cols, 384, true);
        run_conv_bn_relu(w11, Y10, F1N, stats, g11, b11, 128, cols, 256, true);
    }

    // ---------------- FP0: xyz0 (n=8192) <- xyz1 (m=2048) ----------------
    {
        const int n = N0, m = N1, Cskip = 64, Cf = 128, cols = B * n;
        copy_skip_kernel<<<(B * Cskip * n) / 1024, 256>>>(f0, X0, B, Cskip, n);
        knn_interp_kernel<<<dim3(n / 256, B), 256>>>(
            xyz0, xyz1, F1N, X0, n, m, Cf, Cskip, /*fb=*/m, /*fc=*/B * m, B);
        run_conv_bn_relu(w00, X0, Y00, stats, g00, b00, 128, cols, 192, true);
        // final conv: stats then apply with transpose into d_out.
        // Y01 aliases X0 (dead after conv0 GEMM read it).
        run_conv_bn_relu(w01, Y00, Y01, stats, g01, b01, 128, cols, 128, false);
        const int total = 128 * cols;
        bn_apply_out_kernel<<<total / 1024, 256>>>(Y01, stats, g01, b01, out,
                                                   B, 128, n);
    }
}

// round 3
// speedup vs baseline: 1.0009x; 1.0009x over previous
#include <cuda_runtime.h>
#include <cstdint>

// ---------------------------------------------------------------------------
// PointNet++ decoder: 3 FP modules, each = {3-NN interp + concat skip} ->
// conv1x1+BN+ReLU -> conv1x1+BN+ReLU.
// Scratch layout: X is (C_rows, B*N cols) row-major so convs are single GEMMs
// and BN stats are per-row reductions.
// ---------------------------------------------------------------------------

#define B_SZ 8
// level sizes
#define N0 8192
#define N1 2048
#define N2 512
#define N3 128

// scratch buffers (device globals: allocation-free scratch).
// Aliasing to reduce static image size:
//   g_big:   X0 (192 x 65536) during FP0 concat/conv0; then reused as Y01.
//   g_mid:   X2 (768 x 4096) during FP2; then reused as Y10 (256 x 16384).
__device__ float g_big[192 * (B_SZ * N0)];   // 50.3 MB
__device__ float g_Y00[128 * (B_SZ * N0)];   // 33.6 MB
__device__ float g_mid[768 * (B_SZ * N2)];   // 12.6 MB (= 192*16384 floats)
__device__ float g_Y20[256 * (B_SZ * N2)];   // 4.2 MB
__device__ float g_F2N[256 * (B_SZ * N2)];   // 4.2 MB
__device__ float g_X1[384 * (B_SZ * N1)];    // 25.2 MB
__device__ float g_F1N[128 * (B_SZ * N1)];   // 8.4 MB
__device__ float g_stats[2 * 256];           // per-channel {mean, rstd}

// ---------------------------------------------------------------------------
// copy skip features (B,C,N) -> X rows [0,C), layout (C, B*N)
// ---------------------------------------------------------------------------
__global__ void copy_skip_kernel(const float* __restrict__ src,
                                 float* __restrict__ dst,
                                 int B, int C, int N) {
    // dst-linear index, vectorized by 4; totals are multiples of 1024
    size_t t = ((size_t)blockIdx.x * blockDim.x + threadIdx.x) * 4;
    int BN = B * N;
    int c = (int)(t / BN);
    int rem = (int)(t % BN);
    int b = rem / N;
    int n = rem % N;
    *(float4*)(dst + t) =
        *(const float4*)(src + ((size_t)b * C + c) * N + n);
}

// ---------------------------------------------------------------------------
// kNN(3) + inverse-distance interpolation.
// feats indexed as feats[b*fb + c*fc + j]; writes X rows [c0, c0+C)
// with column index b*n + pi (row stride = B*n).
// ---------------------------------------------------------------------------
__global__ void knn_interp_kernel(const float* __restrict__ uxyz,  // (B,n,3)
                                  const float* __restrict__ kxyz,  // (B,m,3)
                                  const float* __restrict__ feats,
                                  float* __restrict__ X,
                                  int n, int m, int C, int c0,
                                  int fb, int fc, int B) {
    __shared__ float skx[2048];
    __shared__ float sky[2048];
    __shared__ float skz[2048];

    const int b = blockIdx.y;
    const int pi = blockIdx.x * blockDim.x + threadIdx.x;

    for (int j = threadIdx.x; j < m; j += blockDim.x) {
        const float* p = kxyz + ((size_t)b * m + j) * 3;
        skx[j] = p[0];
        sky[j] = p[1];
        skz[j] = p[2];
    }
    __syncthreads();
    if (pi >= n) return;

    const float* up = uxyz + ((size_t)b * n + pi) * 3;
    const float ux = up[0], uy = up[1], uz = up[2];

    float d0 = 1e30f, d1 = 1e30f, d2 = 1e30f;
    int i0 = 0, i1 = 0, i2 = 0;
    for (int j = 0; j < m; ++j) {
        float dx = ux - skx[j];
        float dy = uy - sky[j];
        float dz = uz - skz[j];
        float d = dx * dx + dy * dy + dz * dz;
        if (d < d2) {
            if (d < d1) {
                d2 = d1; i2 = i1;
                if (d < d0) { d1 = d0; i1 = i0; d0 = d; i0 = j; }
                else        { d1 = d;  i1 = j; }
            } else {
                d2 = d; i2 = j;
            }
        }
    }

    float r0 = 1.0f / (d0 + 1e-8f);
    float r1 = 1.0f / (d1 + 1e-8f);
    float r2 = 1.0f / (d2 + 1e-8f);
    float rs = 1.0f / (r0 + r1 + r2);
    const float w0 = r0 * rs, w1 = r1 * rs, w2 = r2 * rs;

    const float* fbase = feats + (size_t)b * fb;
    const size_t ocol = (size_t)b * n + pi;
    const size_t rowstride = (size_t)B * n;
    float* outp = X + (size_t)c0 * rowstride + ocol;
    for (int c = 0; c < C; ++c) {
        const float* fr = fbase + (size_t)c * fc;
        outp[(size_t)c * rowstride] = w0 * fr[i0] + w1 * fr[i1] + w2 * fr[i2];
    }
}

// ---------------------------------------------------------------------------
// SGEMM: C(M x N) = A(M x K) @ B(K x N), all row-major fp32.
// BM=BN=64, BK=16, 256 threads, 4x4 micro-tile. All dims are exact multiples.
// ---------------------------------------------------------------------------
__global__ __launch_bounds__(256) void sgemm64_kernel(
    const float* __restrict__ A, const float* __restrict__ B,
    float* __restrict__ C, int M, int N, int K) {
    __shared__ float As[16][64];
    __shared__ float Bs[16][64];

    const int tid = threadIdx.x;
    const int bm = blockIdx.y * 64;
    const int bn = blockIdx.x * 64;
    const int tx = tid & 15;   // 0..15 along N
    const int ty = tid >> 4;   // 0..15 along M
    const int arow = tid >> 2;         // 0..63
    const int acol = (tid & 3) << 2;   // 0,4,8,12
    const int brow = tid >> 4;         // 0..15
    const int bcol = (tid & 15) << 2;  // 0..60

    const float* Aptr = A + (size_t)(bm + arow) * K + acol;
    const float* Bptr = B + (size_t)brow * N + bn + bcol;

    float acc[4][4];
#pragma unroll
    for (int i = 0; i < 4; ++i)
#pragma unroll
        for (int j = 0; j < 4; ++j) acc[i][j] = 0.0f;

    for (int k0 = 0; k0 < K; k0 += 16) {
        float4 a4 = *(const float4*)(Aptr + k0);
        float4 b4 = *(const float4*)(Bptr + (size_t)k0 * N);
        As[acol + 0][arow] = a4.x;
        As[acol + 1][arow] = a4.y;
        As[acol + 2][arow] = a4.z;
        As[acol + 3][arow] = a4.w;
        *(float4*)&Bs[brow][bcol] = b4;
        __syncthreads();
#pragma unroll
        for (int kk = 0; kk < 16; ++kk) {
            float4 av = *(const float4*)&As[kk][ty << 2];
            float4 bv = *(const float4*)&Bs[kk][tx << 2];
            acc[0][0] += av.x * bv.x; acc[0][1] += av.x * bv.y;
            acc[0][2] += av.x * bv.z; acc[0][3] += av.x * bv.w;
            acc[1][0] += av.y * bv.x; acc[1][1] += av.y * bv.y;
            acc[1][2] += av.y * bv.z; acc[1][3] += av.y * bv.w;
            acc[2][0] += av.z * bv.x; acc[2][1] += av.z * bv.y;
            acc[2][2] += av.z * bv.z; acc[2][3] += av.z * bv.w;
            acc[3][0] += av.w * bv.x; acc[3][1] += av.w * bv.y;
            acc[3][2] += av.w * bv.z; acc[3][3] += av.w * bv.w;
        }
        __syncthreads();
    }

#pragma unroll
    for (int i = 0; i < 4; ++i) {
        float4 v = make_float4(acc[i][0], acc[i][1], acc[i][2], acc[i][3]);
        *(float4*)(C + (size_t)(bm + (ty << 2) + i) * N + bn + (tx << 2)) = v;
    }
}

// ---------------------------------------------------------------------------
// BN batch stats: per row (channel) of Y (C x Ncols): mean & rsqrt(var+eps)
// ---------------------------------------------------------------------------
__global__ void bn_stats_kernel(const float* __restrict__ Y,
                                float* __restrict__ stats, int Ncols) {
    const int c = blockIdx.x;
    const float* row = Y + (size_t)c * Ncols;
    float s = 0.0f, s2 = 0.0f;
    for (int i = threadIdx.x * 4; i < Ncols; i += blockDim.x * 4) {
        float4 v = *(const float4*)(row + i);
        s += v.x + v.y + v.z + v.w;
        s2 += v.x * v.x + v.y * v.y + v.z * v.z + v.w * v.w;
    }
#pragma unroll
    for (int o = 16; o; o >>= 1) {
        s += __shfl_down_sync(0xFFFFFFFFu, s, o);
        s2 += __shfl_down_sync(0xFFFFFFFFu, s2, o);
    }
    __shared__ float ws[8], ws2[8];
    const int w = threadIdx.x >> 5, l = threadIdx.x & 31;
    if (l == 0) { ws[w] = s; ws2[w] = s2; }
    __syncthreads();
    if (threadIdx.x == 0) {
        float S = 0.0f, S2 = 0.0f;
        const int nw = blockDim.x >> 5;
        for (int i = 0; i < nw; ++i) { S += ws[i]; S2 += ws2[i]; }
        const float inv = 1.0f / (float)Ncols;
        const float mean = S * inv;
        const float var = S2 * inv - mean * mean;
        stats[2 * c] = mean;
        stats[2 * c + 1] = rsqrtf(var + 1e-5f);
    }
}

// ---------------------------------------------------------------------------
// BN apply + ReLU, in place on (C x Ncols)
// ---------------------------------------------------------------------------
__global__ void bn_apply_ip_kernel(float* __restrict__ Y,
                                   const float* __restrict__ stats,
                                   const float* __restrict__ gamma,
                                   const float* __restrict__ beta,
                                   int Ncols) {
    size_t t = ((size_t)blockIdx.x * blockDim.x + threadIdx.x) * 4;
    const int c = (int)(t / Ncols);
    const float g = gamma[c] * stats[2 * c + 1];
    const float b = beta[c] - stats[2 * c] * g;
    float4 v = *(float4*)(Y + t);
    v.x = fmaxf(v.x * g + b, 0.0f);
    v.y = fmaxf(v.y * g + b, 0.0f);
    v.z = fmaxf(v.z * g + b, 0.0f);
    v.w = fmaxf(v.w * g + b, 0.0f);
    *(float4*)(Y + t) = v;
}

// ---------------------------------------------------------------------------
// BN apply + ReLU, (C, B*N) -> out (B,C,N)
// ---------------------------------------------------------------------------
__global__ void bn_apply_out_kernel(const float* __restrict__ Y,
                                    const float* __restrict__ stats,
                                    const float* __restrict__ gamma,
                                    const float* __restrict__ beta,
                                    float* __restrict__ out,
                                    int B, int C, int N) {
    size_t t = ((size_t)blockIdx.x * blockDim.x + threadIdx.x) * 4;
    const int BN = B * N;
    const int c = (int)(t / BN);
    const int rem = (int)(t % BN);
    const int b = rem / N;
    const int n = rem % N;
    const float g = gamma[c] * stats[2 * c + 1];
    const float bb = beta[c] - stats[2 * c] * g;
    float4 v = *(const float4*)(Y + t);
    v.x = fmaxf(v.x * g + bb, 0.0f);
    v.y = fmaxf(v.y * g + bb, 0.0f);
    v.z = fmaxf(v.z * g + bb, 0.0f);
    v.w = fmaxf(v.w * g + bb, 0.0f);
    *(float4*)(out + ((size_t)b * C + c) * N + n) = v;
}

// ---------------------------------------------------------------------------
// host driver
// ---------------------------------------------------------------------------
static inline void run_conv_bn_relu(const float* W, const float* X, float* Y,
                                    float* stats,
                                    const float* gamma, const float* beta,
                                    int M, int Ncols, int K, bool apply_ip) {
    dim3 ggrid(Ncols / 64, M / 64);
    sgemm64_kernel<<<ggrid, 256>>>(W, X, Y, M, Ncols, K);
    bn_stats_kernel<<<M, 256>>>(Y, stats, Ncols);
    if (apply_ip) {
        int total = M * Ncols;
        bn_apply_ip_kernel<<<total / 1024, 256>>>(Y, stats, gamma, beta, Ncols);
    }
}

extern "C" void kernel_launch(void* const* d_in, const int* in_sizes, int n_in,
                              void* d_out, int out_size) {
    const float* in[26];
    for (int i = 0; i < 26 && i < n_in; ++i) in[i] = (const float*)d_in[i];

    // Resolve input ordering: interleaved (setup_inputs dict) vs grouped
    // (reference signature). f0 has 4,194,304 elements; xyz1 has 49,152.
    const float *xyz0, *xyz1, *xyz2, *xyz3, *f0, *f1, *f2, *f3;
    if (in_sizes[1] == 8 * 64 * 8192) {  // interleaved: xyz0,f0,xyz1,f1,...
        xyz0 = in[0]; f0 = in[1]; xyz1 = in[2]; f1 = in[3];
        xyz2 = in[4]; f2 = in[5]; xyz3 = in[6]; f3 = in[7];
    } else {  // grouped: xyz0..xyz3, f0..f3
        xyz0 = in[0]; xyz1 = in[1]; xyz2 = in[2]; xyz3 = in[3];
        f0 = in[4]; f1 = in[5]; f2 = in[6]; f3 = in[7];
    }
    const float *w00 = in[8],  *g00 = in[9],  *b00 = in[10];
    const float *w01 = in[11], *g01 = in[12], *b01 = in[13];
    const float *w10 = in[14], *g10 = in[15], *b10 = in[16];
    const float *w11 = in[17], *g11 = in[18], *b11 = in[19];
    const float *w20 = in[20], *g20 = in[21], *b20 = in[22];
    const float *w21 = in[23], *g21 = in[24], *b21 = in[25];

    float *big, *Y00, *mid, *Y20, *F2N, *X1, *F1N, *stats;
    cudaGetSymbolAddress((void**)&big, g_big);
    cudaGetSymbolAddress((void**)&Y00, g_Y00);
    cudaGetSymbolAddress((void**)&mid, g_mid);
    cudaGetSymbolAddress((void**)&Y20, g_Y20);
    cudaGetSymbolAddress((void**)&F2N, g_F2N);
    cudaGetSymbolAddress((void**)&X1, g_X1);
    cudaGetSymbolAddress((void**)&F1N, g_F1N);
    cudaGetSymbolAddress((void**)&stats, g_stats);

    // Aliased views (see buffer comments above):
    float* X2  = mid;   // 768 x 4096 during FP2
    float* Y10 = mid;   // 256 x 16384 during FP1 (X2 dead by then)
    float* X0  = big;   // 192 x 65536 during FP0 concat + conv0
    float* Y01 = big;   // 128 x 65536 after conv0 (X0 dead as GEMM input? no —
                        // X0 is read by conv0 GEMM, Y01 written by conv1 GEMM
                        // which reads Y00 only; X0 is dead at that point)

    float* out = (float*)d_out;
    const int B = B_SZ;

    // ---------------- FP2: xyz2 (n=512) <- xyz3 (m=128) ----------------
    {
        const int n = N2, m = N3, Cskip = 256, Cf = 512, cols = B * n;
        copy_skip_kernel<<<(B * Cskip * n) / 1024, 256>>>(f2, X2, B, Cskip, n);
        knn_interp_kernel<<<dim3(n / 256, B), 256>>>(
            xyz2, xyz3, f3, X2, n, m, Cf, Cskip, /*fb=*/Cf * m, /*fc=*/m, B);
        run_conv_bn_relu(w20, X2, Y20, stats, g20, b20, 256, cols, 768, true);
        run_conv_bn_relu(w21, Y20, F2N, stats, g21, b21, 256, cols, 256, true);
    }

    // ---------------- FP1: xyz1 (n=2048) <- xyz2 (m=512) ----------------
    {
        const int n = N1, m = N2, Cskip = 128, Cf = 256, cols = B * n;
        copy_skip_kernel<<<(B * Cskip * n) / 1024, 256>>>(f1, X1, B, Cskip, n);
        knn_interp_kernel<<<dim3(n / 256, B), 256>>>(
            xyz1, xyz2, F2N, X1, n, m, Cf, Cskip, /*fb=*/m, /*fc=*/B * m, B);
        run_conv_bn_relu(w10, X1, Y10, stats, g10, b10, 256, cols, 384, true);
        run_conv_bn_relu(w11, Y10, F1N, stats, g11, b11, 128, cols, 256, true);
    }

    // ---------------- FP0: xyz0 (n=8192) <- xyz1 (m=2048) ----------------
    {
        const int n = N0, m = N1, Cskip = 64, Cf = 128, cols = B * n;
        copy_skip_kernel<<<(B * Cskip * n) / 1024, 256>>>(f0, X0, B, Cskip, n);
        knn_interp_kernel<<<dim3(n / 256, B), 256>>>(
            xyz0, xyz1, F1N, X0, n, m, Cf, Cskip, /*fb=*/m, /*fc=*/B * m, B);
        run_conv_bn_relu(w00, X0, Y00, stats, g00, b00, 128, cols, 192, true);
        // final conv: stats then apply with transpose into d_out.
        // Y01 aliases X0 (dead after conv0 GEMM read it).
        run_conv_bn_relu(w01, Y00, Y01, stats, g01, b01, 128, cols, 128, false);
        const int total = 128 * cols;
        bn_apply_out_kernel<<<total / 1024, 256>>>(Y01, stats, g01, b01, out,
                                                   B, 128, n);
    }
}

// round 4
// speedup vs baseline: 1.0023x; 1.0014x over previous
#include <cuda_runtime.h>
#include <cstdint>

// ---------------------------------------------------------------------------
// PointNet++ decoder: 3 FP modules, each = {3-NN interp + concat skip} ->
// conv1x1+BN+ReLU -> conv1x1+BN+ReLU.
// Scratch layout: X is (C_rows, B*N cols) row-major so convs are single GEMMs
// and BN stats are per-row reductions.
// ---------------------------------------------------------------------------

#define B_SZ 8
// level sizes
#define N0 8192
#define N1 2048
#define N2 512
#define N3 128

// scratch buffers (device globals: allocation-free scratch).
// Aliasing to reduce static image size:
//   g_big:   X0 (192 x 65536) during FP0 concat/conv0; then reused as Y01.
//   g_mid:   X2 (768 x 4096) during FP2; then reused as Y10 (256 x 16384).
__device__ float g_big[192 * (B_SZ * N0)];   // 50.3 MB
__device__ float g_Y00[128 * (B_SZ * N0)];   // 33.6 MB
__device__ float g_mid[768 * (B_SZ * N2)];   // 12.6 MB (= 192*16384 floats)
__device__ float g_Y20[256 * (B_SZ * N2)];   // 4.2 MB
__device__ float g_F2N[256 * (B_SZ * N2)];   // 4.2 MB
__device__ float g_X1[384 * (B_SZ * N1)];    // 25.2 MB
__device__ float g_F1N[128 * (B_SZ * N1)];   // 8.4 MB
__device__ float g_stats[2 * 256];           // per-channel {mean, rstd}

// ---------------------------------------------------------------------------
// copy skip features (B,C,N) -> X rows [0,C), layout (C, B*N)
// ---------------------------------------------------------------------------
__global__ void copy_skip_kernel(const float* __restrict__ src,
                                 float* __restrict__ dst,
                                 int B, int C, int N) {
    // dst-linear index, vectorized by 4; totals are multiples of 1024
    size_t t = ((size_t)blockIdx.x * blockDim.x + threadIdx.x) * 4;
    int BN = B * N;
    int c = (int)(t / BN);
    int rem = (int)(t % BN);
    int b = rem / N;
    int n = rem % N;
    *(float4*)(dst + t) =
        *(const float4*)(src + ((size_t)b * C + c) * N + n);
}

// ---------------------------------------------------------------------------
// kNN(3) + inverse-distance interpolation.
// feats indexed as feats[b*fb + c*fc + j]; writes X rows [c0, c0+C)
// with column index b*n + pi (row stride = B*n).
// ---------------------------------------------------------------------------
__global__ void knn_interp_kernel(const float* __restrict__ uxyz,  // (B,n,3)
                                  const float* __restrict__ kxyz,  // (B,m,3)
                                  const float* __restrict__ feats,
                                  float* __restrict__ X,
                                  int n, int m, int C, int c0,
                                  int fb, int fc, int B) {
    __shared__ float skx[2048];
    __shared__ float sky[2048];
    __shared__ float skz[2048];

    const int b = blockIdx.y;
    const int pi = blockIdx.x * blockDim.x + threadIdx.x;

    for (int j = threadIdx.x; j < m; j += blockDim.x) {
        const float* p = kxyz + ((size_t)b * m + j) * 3;
        skx[j] = p[0];
        sky[j] = p[1];
        skz[j] = p[2];
    }
    __syncthreads();
    if (pi >= n) return;

    const float* up = uxyz + ((size_t)b * n + pi) * 3;
    const float ux = up[0], uy = up[1], uz = up[2];

    float d0 = 1e30f, d1 = 1e30f, d2 = 1e30f;
    int i0 = 0, i1 = 0, i2 = 0;
    for (int j = 0; j < m; ++j) {
        float dx = ux - skx[j];
        float dy = uy - sky[j];
        float dz = uz - skz[j];
        float d = dx * dx + dy * dy + dz * dz;
        if (d < d2) {
            if (d < d1) {
                d2 = d1; i2 = i1;
                if (d < d0) { d1 = d0; i1 = i0; d0 = d; i0 = j; }
                else        { d1 = d;  i1 = j; }
            } else {
                d2 = d; i2 = j;
            }
        }
    }

    float r0 = 1.0f / (d0 + 1e-8f);
    float r1 = 1.0f / (d1 + 1e-8f);
    float r2 = 1.0f / (d2 + 1e-8f);
    float rs = 1.0f / (r0 + r1 + r2);
    const float w0 = r0 * rs, w1 = r1 * rs, w2 = r2 * rs;

    const float* fbase = feats + (size_t)b * fb;
    const size_t ocol = (size_t)b * n + pi;
    const size_t rowstride = (size_t)B * n;
    float* outp = X + (size_t)c0 * rowstride + ocol;
    for (int c = 0; c < C; ++c) {
        const float* fr = fbase + (size_t)c * fc;
        outp[(size_t)c * rowstride] = w0 * fr[i0] + w1 * fr[i1] + w2 * fr[i2];
    }
}

// ---------------------------------------------------------------------------
// SGEMM: C(M x N) = A(M x K) @ B(K x N), all row-major fp32.
// BM=BN=64, BK=16, 256 threads, 4x4 micro-tile. All dims are exact multiples.
// ---------------------------------------------------------------------------
__global__ __launch_bounds__(256) void sgemm64_kernel(
    const float* __restrict__ A, const float* __restrict__ B,
    float* __restrict__ C, int M, int N, int K) {
    __shared__ float As[16][64];
    __shared__ float Bs[16][64];

    const int tid = threadIdx.x;
    const int bm = blockIdx.y * 64;
    const int bn = blockIdx.x * 64;
    const int tx = tid & 15;   // 0..15 along N
    const int ty = tid >> 4;   // 0..15 along M
    const int arow = tid >> 2;         // 0..63
    const int acol = (tid & 3) << 2;   // 0,4,8,12
    const int brow = tid >> 4;         // 0..15
    const int bcol = (tid & 15) << 2;  // 0..60

    const float* Aptr = A + (size_t)(bm + arow) * K + acol;
    const float* Bptr = B + (size_t)brow * N + bn + bcol;

    float acc[4][4];
#pragma unroll
    for (int i = 0; i < 4; ++i)
#pragma unroll
        for (int j = 0; j < 4; ++j) acc[i][j] = 0.0f;

    for (int k0 = 0; k0 < K; k0 += 16) {
        float4 a4 = *(const float4*)(Aptr + k0);
        float4 b4 = *(const float4*)(Bptr + (size_t)k0 * N);
        As[acol + 0][arow] = a4.x;
        As[acol + 1][arow] = a4.y;
        As[acol + 2][arow] = a4.z;
        As[acol + 3][arow] = a4.w;
        *(float4*)&Bs[brow][bcol] = b4;
        __syncthreads();
#pragma unroll
        for (int kk = 0; kk < 16; ++kk) {
            float4 av = *(const float4*)&As[kk][ty << 2];
            float4 bv = *(const float4*)&Bs[kk][tx << 2];
            acc[0][0] += av.x * bv.x; acc[0][1] += av.x * bv.y;
            acc[0][2] += av.x * bv.z; acc[0][3] += av.x * bv.w;
            acc[1][0] += av.y * bv.x; acc[1][1] += av.y * bv.y;
            acc[1][2] += av.y * bv.z; acc[1][3] += av.y * bv.w;
            acc[2][0] += av.z * bv.x; acc[2][1] += av.z * bv.y;
            acc[2][2] += av.z * bv.z; acc[2][3] += av.z * bv.w;
            acc[3][0] += av.w * bv.x; acc[3][1] += av.w * bv.y;
            acc[3][2] += av.w * bv.z; acc[3][3] += av.w * bv.w;
        }
        __syncthreads();
    }

#pragma unroll
    for (int i = 0; i < 4; ++i) {
        float4 v = make_float4(acc[i][0], acc[i][1], acc[i][2], acc[i][3]);
        *(float4*)(C + (size_t)(bm + (ty << 2) + i) * N + bn + (tx << 2)) = v;
    }
}

// ---------------------------------------------------------------------------
// BN batch stats: per row (channel) of Y (C x Ncols): mean & rsqrt(var+eps)
// ---------------------------------------------------------------------------
__global__ void bn_stats_kernel(const float* __restrict__ Y,
                                float* __restrict__ stats, int Ncols) {
    const int c = blockIdx.x;
    const float* row = Y + (size_t)c * Ncols;
    float s = 0.0f, s2 = 0.0f;
    for (int i = threadIdx.x * 4; i < Ncols; i += blockDim.x * 4) {
        float4 v = *(const float4*)(row + i);
        s += v.x + v.y + v.z + v.w;
        s2 += v.x * v.x + v.y * v.y + v.z * v.z + v.w * v.w;
    }
#pragma unroll
    for (int o = 16; o; o >>= 1) {
        s += __shfl_down_sync(0xFFFFFFFFu, s, o);
        s2 += __shfl_down_sync(0xFFFFFFFFu, s2, o);
    }
    __shared__ float ws[8], ws2[8];
    const int w = threadIdx.x >> 5, l = threadIdx.x & 31;
    if (l == 0) { ws[w] = s; ws2[w] = s2; }
    __syncthreads();
    if (threadIdx.x == 0) {
        float S = 0.0f, S2 = 0.0f;
        const int nw = blockDim.x >> 5;
        for (int i = 0; i < nw; ++i) { S += ws[i]; S2 += ws2[i]; }
        const float inv = 1.0f / (float)Ncols;
        const float mean = S * inv;
        const float var = S2 * inv - mean * mean;
        stats[2 * c] = mean;
        stats[2 * c + 1] = rsqrtf(var + 1e-5f);
    }
}

// ---------------------------------------------------------------------------
// BN apply + ReLU, in place on (C x Ncols)
// ---------------------------------------------------------------------------
__global__ void bn_apply_ip_kernel(float* __restrict__ Y,
                                   const float* __restrict__ stats,
                                   const float* __restrict__ gamma,
                                   const float* __restrict__ beta,
                                   int Ncols) {
    size_t t = ((size_t)blockIdx.x * blockDim.x + threadIdx.x) * 4;
    const int c = (int)(t / Ncols);
    const float g = gamma[c] * stats[2 * c + 1];
    const float b = beta[c] - stats[2 * c] * g;
    float4 v = *(float4*)(Y + t);
    v.x = fmaxf(v.x * g + b, 0.0f);
    v.y = fmaxf(v.y * g + b, 0.0f);
    v.z = fmaxf(v.z * g + b, 0.0f);
    v.w = fmaxf(v.w * g + b, 0.0f);
    *(float4*)(Y + t) = v;
}

// ---------------------------------------------------------------------------
// BN apply + ReLU, (C, B*N) -> out (B,C,N)
// ---------------------------------------------------------------------------
__global__ void bn_apply_out_kernel(const float* __restrict__ Y,
                                    const float* __restrict__ stats,
                                    const float* __restrict__ gamma,
                                    const float* __restrict__ beta,
                                    float* __restrict__ out,
                                    int B, int C, int N) {
    size_t t = ((size_t)blockIdx.x * blockDim.x + threadIdx.x) * 4;
    const int BN = B * N;
    const int c = (int)(t / BN);
    const int rem = (int)(t % BN);
    const int b = rem / N;
    const int n = rem % N;
    const float g = gamma[c] * stats[2 * c + 1];
    const float bb = beta[c] - stats[2 * c] * g;
    float4 v = *(const float4*)(Y + t);
    v.x = fmaxf(v.x * g + bb, 0.0f);
    v.y = fmaxf(v.y * g + bb, 0.0f);
    v.z = fmaxf(v.z * g + bb, 0.0f);
    v.w = fmaxf(v.w * g + bb, 0.0f);
    *(float4*)(out + ((size_t)b * C + c) * N + n) = v;
}

// ---------------------------------------------------------------------------
// host driver
// ---------------------------------------------------------------------------
static inline void run_conv_bn_relu(const float* W, const float* X, float* Y,
                                    float* stats,
                                    const float* gamma, const float* beta,
                                    int M, int Ncols, int K, bool apply_ip) {
    dim3 ggrid(Ncols / 64, M / 64);
    sgemm64_kernel<<<ggrid, 256>>>(W, X, Y, M, Ncols, K);
    bn_stats_kernel<<<M, 256>>>(Y, stats, Ncols);
    if (apply_ip) {
        int total = M * Ncols;
        bn_apply_ip_kernel<<<total / 1024, 256>>>(Y, stats, gamma, beta, Ncols);
    }
}

extern "C" void kernel_launch(void* const* d_in, const int* in_sizes, int n_in,
                              void* d_out, int out_size) {
    const float* in[26];
    for (int i = 0; i < 26 && i < n_in; ++i) in[i] = (const float*)d_in[i];

    // Resolve input ordering: interleaved (setup_inputs dict) vs grouped
    // (reference signature). f0 has 4,194,304 elements; xyz1 has 49,152.
    const float *xyz0, *xyz1, *xyz2, *xyz3, *f0, *f1, *f2, *f3;
    if (in_sizes[1] == 8 * 64 * 8192) {  // interleaved: xyz0,f0,xyz1,f1,...
        xyz0 = in[0]; f0 = in[1]; xyz1 = in[2]; f1 = in[3];
        xyz2 = in[4]; f2 = in[5]; xyz3 = in[6]; f3 = in[7];
    } else {  // grouped: xyz0..xyz3, f0..f3
        xyz0 = in[0]; xyz1 = in[1]; xyz2 = in[2]; xyz3 = in[3];
        f0 = in[4]; f1 = in[5]; f2 = in[6]; f3 = in[7];
    }
    const float *w00 = in[8],  *g00 = in[9],  *b00 = in[10];
    const float *w01 = in[11], *g01 = in[12], *b01 = in[13];
    const float *w10 = in[14], *g10 = in[15], *b10 = in[16];
    const float *w11 = in[17], *g11 = in[18], *b11 = in[19];
    const float *w20 = in[20], *g20 = in[21], *b20 = in[22];
    const float *w21 = in[23], *g21 = in[24], *b21 = in[25];

    float *big, *Y00, *mid, *Y20, *F2N, *X1, *F1N, *stats;
    cudaGetSymbolAddress((void**)&big, g_big);
    cudaGetSymbolAddress((void**)&Y00, g_Y00);
    cudaGetSymbolAddress((void**)&mid, g_mid);
    cudaGetSymbolAddress((void**)&Y20, g_Y20);
    cudaGetSymbolAddress((void**)&F2N, g_F2N);
    cudaGetSymbolAddress((void**)&X1, g_X1);
    cudaGetSymbolAddress((void**)&F1N, g_F1N);
    cudaGetSymbolAddress((void**)&stats, g_stats);

    // Aliased views (see buffer comments above):
    float* X2  = mid;   // 768 x 4096 during FP2
    float* Y10 = mid;   // 256 x 16384 during FP1 (X2 dead by then)
    float* X0  = big;   // 192 x 65536 during FP0 concat + conv0
    float* Y01 = big;   // 128 x 65536 after conv0 (X0 dead as GEMM input? no —
                        // X0 is read by conv0 GEMM, Y01 written by conv1 GEMM
                        // which reads Y00 only; X0 is dead at that point)

    float* out = (float*)d_out;
    const int B = B_SZ;

    // ---------------- FP2: xyz2 (n=512) <- xyz3 (m=128) ----------------
    {
        const int n = N2, m = N3, Cskip = 256, Cf = 512, cols = B * n;
        copy_skip_kernel<<<(B * Cskip * n) / 1024, 256>>>(f2, X2, B, Cskip, n);
        knn_interp_kernel<<<dim3(n / 256, B), 256>>>(
            xyz2, xyz3, f3, X2, n, m, Cf, Cskip, /*fb=*/Cf * m, /*fc=*/m, B);
        run_conv_bn_relu(w20, X2, Y20, stats, g20, b20, 256, cols, 768, true);
        run_conv_bn_relu(w21, Y20, F2N, stats, g21, b21, 256, cols, 256, true);
    }

    // ---------------- FP1: xyz1 (n=2048) <- xyz2 (m=512) ----------------
    {
        const int n = N1, m = N2, Cskip = 128, Cf = 256, cols = B * n;
        copy_skip_kernel<<<(B * Cskip * n) / 1024, 256>>>(f1, X1, B, Cskip, n);
        knn_interp_kernel<<<dim3(n / 256, B), 256>>>(
            xyz1, xyz2, F2N, X1, n, m, Cf, Cskip, /*fb=*/m, /*fc=*/B * m, B);
        run_conv_bn_relu(w10, X1, Y10, stats, g10, b10, 256, cols, 384, true);
        run_conv_bn_relu(w11, Y10, F1N, stats, g11, b11, 128, cols, 256, true);
    }

    // ---------------- FP0: xyz0 (n=8192) <- xyz1 (m=2048) ----------------
    {
        const int n = N0, m = N1, Cskip = 64, Cf = 128, cols = B * n;
        copy_skip_kernel<<<(B * Cskip * n) / 1024, 256>>>(f0, X0, B, Cskip, n);
        knn_interp_kernel<<<dim3(n / 256, B), 256>>>(
            xyz0, xyz1, F1N, X0, n, m, Cf, Cskip, /*fb=*/m, /*fc=*/B * m, B);
        run_conv_bn_relu(w00, X0, Y00, stats, g00, b00, 128, cols, 192, true);
        // final conv: stats then apply with transpose into d_out.
        // Y01 aliases X0 (dead after conv0 GEMM read it).
        run_conv_bn_relu(w01, Y00, Y01, stats, g01, b01, 128, cols, 128, false);
        const int total = 128 * cols;
        bn_apply_out_kernel<<<total / 1024, 256>>>(Y01, stats, g01, b01, out,
                                                   B, 128, n);
    }
}

// round 6
// speedup vs baseline: 1.1942x; 1.1914x over previous
#include <cuda_runtime.h>
#include <cstdint>

// ---------------------------------------------------------------------------
// PointNet++ decoder: 3 FP modules, each = {3-NN interp + concat skip} ->
// conv1x1+BN+ReLU -> conv1x1+BN+ReLU.
// Scratch layout: X is (C_rows, B*N cols) row-major so convs are single GEMMs
// and BN stats are per-row reductions. GEMMs run on tensor cores (tf32 mma).
// ---------------------------------------------------------------------------

#define B_SZ 8
// level sizes
#define N0 8192
#define N1 2048
#define N2 512
#define N3 128

// scratch buffers (device globals: allocation-free scratch).
// Aliasing to reduce static image size:
//   g_big:   X0 (192 x 65536) during FP0 concat/conv0; then reused as Y01.
//   g_mid:   X2 (768 x 4096) during FP2; then reused as Y10 (256 x 16384).
__device__ float g_big[192 * (B_SZ * N0)];   // 50.3 MB
__device__ float g_Y00[128 * (B_SZ * N0)];   // 33.6 MB
__device__ float g_mid[768 * (B_SZ * N2)];   // 12.6 MB (= 192*16384 floats)
__device__ float g_Y20[256 * (B_SZ * N2)];   // 4.2 MB
__device__ float g_F2N[256 * (B_SZ * N2)];   // 4.2 MB
__device__ float g_X1[384 * (B_SZ * N1)];    // 25.2 MB
__device__ float g_F1N[128 * (B_SZ * N1)];   // 8.4 MB
__device__ float g_stats[2 * 256];           // per-channel {mean, rstd}

// ---------------------------------------------------------------------------
// copy skip features (B,C,N) -> X rows [0,C), layout (C, B*N)
// ---------------------------------------------------------------------------
__global__ void copy_skip_kernel(const float* __restrict__ src,
                                 float* __restrict__ dst,
                                 int B, int C, int N) {
    size_t t = ((size_t)blockIdx.x * blockDim.x + threadIdx.x) * 4;
    int BN = B * N;
    int c = (int)(t / BN);
    int rem = (int)(t % BN);
    int b = rem / N;
    int n = rem % N;
    *(float4*)(dst + t) =
        *(const float4*)(src + ((size_t)b * C + c) * N + n);
}

// ---------------------------------------------------------------------------
// kNN(3) + inverse-distance interpolation.
// feats indexed as feats[b*fb + c*fc + j]; writes X rows [c0, c0+C)
// with column index b*n + pi (row stride = B*n).
// ---------------------------------------------------------------------------
__global__ void knn_interp_kernel(const float* __restrict__ uxyz,  // (B,n,3)
                                  const float* __restrict__ kxyz,  // (B,m,3)
                                  const float* __restrict__ feats,
                                  float* __restrict__ X,
                                  int n, int m, int C, int c0,
                                  int fb, int fc, int B) {
    __shared__ float skx[2048];
    __shared__ float sky[2048];
    __shared__ float skz[2048];

    const int b = blockIdx.y;
    const int pi = blockIdx.x * blockDim.x + threadIdx.x;

    for (int j = threadIdx.x; j < m; j += blockDim.x) {
        const float* p = kxyz + ((size_t)b * m + j) * 3;
        skx[j] = p[0];
        sky[j] = p[1];
        skz[j] = p[2];
    }
    __syncthreads();
    if (pi >= n) return;

    const float* up = uxyz + ((size_t)b * n + pi) * 3;
    const float ux = up[0], uy = up[1], uz = up[2];

    float d0 = 1e30f, d1 = 1e30f, d2 = 1e30f;
    int i0 = 0, i1 = 0, i2 = 0;
    for (int j = 0; j < m; ++j) {
        float dx = ux - skx[j];
        float dy = uy - sky[j];
        float dz = uz - skz[j];
        float d = dx * dx + dy * dy + dz * dz;
        if (d < d2) {
            if (d < d1) {
                d2 = d1; i2 = i1;
                if (d < d0) { d1 = d0; i1 = i0; d0 = d; i0 = j; }
                else        { d1 = d;  i1 = j; }
            } else {
                d2 = d; i2 = j;
            }
        }
    }

    float r0 = 1.0f / (d0 + 1e-8f);
    float r1 = 1.0f / (d1 + 1e-8f);
    float r2 = 1.0f / (d2 + 1e-8f);
    float rs = 1.0f / (r0 + r1 + r2);
    const float w0 = r0 * rs, w1 = r1 * rs, w2 = r2 * rs;

    const float* fbase = feats + (size_t)b * fb;
    const size_t ocol = (size_t)b * n + pi;
    const size_t rowstride = (size_t)B * n;
    float* outp = X + (size_t)c0 * rowstride + ocol;
    for (int c = 0; c < C; ++c) {
        const float* fr = fbase + (size_t)c * fc;
        outp[(size_t)c * rowstride] = w0 * fr[i0] + w1 * fr[i1] + w2 * fr[i2];
    }
}

// ---------------------------------------------------------------------------
// tf32 tensor-core GEMM: C(M x N) = A(M x K) @ B(K x N), row-major fp32 I/O.
// CTA tile 128x128x32, 256 threads, 8 warps (2 M x 4 N), warp tile 64x32.
// mma.sync.m16n8k8 tf32. Shared tiles stored transposed with row stride 136
// floats so fragment loads (k=lane&3, m|n=lane>>2 -> bank 8k+m) hit all 32
// banks conflict-free. All problem dims are exact multiples of the tiles.
// ---------------------------------------------------------------------------
#define SROW 136  // shared row stride (floats) for 32-row k-major tiles

__device__ __forceinline__ float to_tf32(float x) {
    uint32_t u;
    asm("cvt.rna.tf32.f32 %0, %1;" : "=r"(u) : "f"(x));
    return __uint_as_float(u);
}

__global__ __launch_bounds__(256) void gemm_tf32_kernel(
    const float* __restrict__ A, const float* __restrict__ Bm,
    float* __restrict__ C, int M, int N, int K) {
    __shared__ float As[32 * SROW];  // As[k][m], m in [0,128)
    __shared__ float Bs[32 * SROW];  // Bs[k][n], n in [0,128)

    const int tid = threadIdx.x;
    const int lane = tid & 31;
    const int wid = tid >> 5;
    const int bm = blockIdx.y * 128;
    const int bn = blockIdx.x * 128;
    const int wm = (wid >> 2) * 64;   // warp M offset in tile (0 or 64)
    const int wn = (wid & 3) * 32;    // warp N offset in tile (0..96)

    // A loader: thread t -> row (t&127), k-half (t>>7)*16
    const int a_row = tid & 127;
    const int a_kh = (tid >> 7) << 4;
    // B loader: thread t -> k-row (t>>3), col offset (t&7)*16
    const int b_kr = tid >> 3;
    const int b_co = (tid & 7) << 4;

    const int g = lane >> 2;   // group id (0..7)
    const int tg = lane & 3;   // thread-in-group (0..3)

    float acc[4][4][4];
#pragma unroll
    for (int i = 0; i < 4; ++i)
#pragma unroll
        for (int j = 0; j < 4; ++j)
#pragma unroll
            for (int r = 0; r < 4; ++r) acc[i][j][r] = 0.0f;

    for (int k0 = 0; k0 < K; k0 += 32) {
        // ---- load A tile (128 x 32) -> As[k][m], tf32-converted ----
        {
            const float* ap = A + (size_t)(bm + a_row) * K + k0 + a_kh;
#pragma unroll
            for (int v = 0; v < 4; ++v) {
                float4 x = *(const float4*)(ap + v * 4);
                As[(a_kh + v * 4 + 0) * SROW + a_row] = to_tf32(x.x);
                As[(a_kh + v * 4 + 1) * SROW + a_row] = to_tf32(x.y);
                As[(a_kh + v * 4 + 2) * SROW + a_row] = to_tf32(x.z);
                As[(a_kh + v * 4 + 3) * SROW + a_row] = to_tf32(x.w);
            }
        }
        // ---- load B tile (32 x 128) -> Bs[k][n], tf32-converted ----
        {
            const float* bp = Bm + (size_t)(k0 + b_kr) * N + bn + b_co;
#pragma unroll
            for (int v = 0; v < 4; ++v) {
                float4 x = *(const float4*)(bp + v * 4);
                x.x = to_tf32(x.x); x.y = to_tf32(x.y);
                x.z = to_tf32(x.z); x.w = to_tf32(x.w);
                *(float4*)&Bs[b_kr * SROW + b_co + v * 4] = x;
            }
        }
        __syncthreads();

#pragma unroll
        for (int ks = 0; ks < 4; ++ks) {
            const int kb = ks * 8;
            uint32_t af[4][4];
            uint32_t bf[4][2];
#pragma unroll
            for (int mt = 0; mt < 4; ++mt) {
                const int mr = wm + mt * 16 + g;
                af[mt][0] = __float_as_uint(As[(kb + tg) * SROW + mr]);
                af[mt][1] = __float_as_uint(As[(kb + tg) * SROW + mr + 8]);
                af[mt][2] = __float_as_uint(As[(kb + tg + 4) * SROW + mr]);
                af[mt][3] = __float_as_uint(As[(kb + tg + 4) * SROW + mr + 8]);
            }
#pragma unroll
            for (int nt = 0; nt < 4; ++nt) {
                const int nc = wn + nt * 8 + g;
                bf[nt][0] = __float_as_uint(Bs[(kb + tg) * SROW + nc]);
                bf[nt][1] = __float_as_uint(Bs[(kb + tg + 4) * SROW + nc]);
            }
#pragma unroll
            for (int mt = 0; mt < 4; ++mt)
#pragma unroll
                for (int nt = 0; nt < 4; ++nt) {
                    asm volatile(
                        "mma.sync.aligned.m16n8k8.row.col.f32.tf32.tf32.f32 "
                        "{%0,%1,%2,%3}, {%4,%5,%6,%7}, {%8,%9}, {%0,%1,%2,%3};"
                        : "+f"(acc[mt][nt][0]), "+f"(acc[mt][nt][1]),
                          "+f"(acc[mt][nt][2]), "+f"(acc[mt][nt][3])
                        : "r"(af[mt][0]), "r"(af[mt][1]),
                          "r"(af[mt][2]), "r"(af[mt][3]),
                          "r"(bf[nt][0]), "r"(bf[nt][1]));
                }
        }
        __syncthreads();
    }

    // ---- epilogue: write C fragments ----
#pragma unroll
    for (int mt = 0; mt < 4; ++mt) {
        const int row = bm + wm + mt * 16 + g;
#pragma unroll
        for (int nt = 0; nt < 4; ++nt) {
            const int col = bn + wn + nt * 8 + tg * 2;
            *(float2*)(C + (size_t)row * N + col) =
                make_float2(acc[mt][nt][0], acc[mt][nt][1]);
            *(float2*)(C + (size_t)(row + 8) * N + col) =
                make_float2(acc[mt][nt][2], acc[mt][nt][3]);
        }
    }
}

// ---------------------------------------------------------------------------
// BN batch stats: per row (channel) of Y (C x Ncols): mean & rsqrt(var+eps)
// ---------------------------------------------------------------------------
__global__ void bn_stats_kernel(const float* __restrict__ Y,
                                float* __restrict__ stats, int Ncols) {
    const int c = blockIdx.x;
    const float* row = Y + (size_t)c * Ncols;
    float s = 0.0f, s2 = 0.0f;
    for (int i = threadIdx.x * 4; i < Ncols; i += blockDim.x * 4) {
        float4 v = *(const float4*)(row + i);
        s += v.x + v.y + v.z + v.w;
        s2 += v.x * v.x + v.y * v.y + v.z * v.z + v.w * v.w;
    }
#pragma unroll
    for (int o = 16; o; o >>= 1) {
        s += __shfl_down_sync(0xFFFFFFFFu, s, o);
        s2 += __shfl_down_sync(0xFFFFFFFFu, s2, o);
    }
    __shared__ float ws[8], ws2[8];
    const int w = threadIdx.x >> 5, l = threadIdx.x & 31;
    if (l == 0) { ws[w] = s; ws2[w] = s2; }
    __syncthreads();
    if (threadIdx.x == 0) {
        float S = 0.0f, S2 = 0.0f;
        const int nw = blockDim.x >> 5;
        for (int i = 0; i < nw; ++i) { S += ws[i]; S2 += ws2[i]; }
        const float inv = 1.0f / (float)Ncols;
        const float mean = S * inv;
        const float var = S2 * inv - mean * mean;
        stats[2 * c] = mean;
        stats[2 * c + 1] = rsqrtf(var + 1e-5f);
    }
}

// ---------------------------------------------------------------------------
// BN apply + ReLU, in place on (C x Ncols)
// ---------------------------------------------------------------------------
__global__ void bn_apply_ip_kernel(float* __restrict__ Y,
                                   const float* __restrict__ stats,
                                   const float* __restrict__ gamma,
                                   const float* __restrict__ beta,
                                   int Ncols) {
    size_t t = ((size_t)blockIdx.x * blockDim.x + threadIdx.x) * 4;
    const int c = (int)(t / Ncols);
    const float g = gamma[c] * stats[2 * c + 1];
    const float b = beta[c] - stats[2 * c] * g;
    float4 v = *(float4*)(Y + t);
    v.x = fmaxf(v.x * g + b, 0.0f);
    v.y = fmaxf(v.y * g + b, 0.0f);
    v.z = fmaxf(v.z * g + b, 0.0f);
    v.w = fmaxf(v.w * g + b, 0.0f);
    *(float4*)(Y + t) = v;
}

// ---------------------------------------------------------------------------
// BN apply + ReLU, (C, B*N) -> out (B,C,N)
// ---------------------------------------------------------------------------
__global__ void bn_apply_out_kernel(const float* __restrict__ Y,
                                    const float* __restrict__ stats,
                                    const float* __restrict__ gamma,
                                    const float* __restrict__ beta,
                                    float* __restrict__ out,
                                    int B, int C, int N) {
    size_t t = ((size_t)blockIdx.x * blockDim.x + threadIdx.x) * 4;
    const int BN = B * N;
    const int c = (int)(t / BN);
    const int rem = (int)(t % BN);
    const int b = rem / N;
    const int n = rem % N;
    const float g = gamma[c] * stats[2 * c + 1];
    const float bb = beta[c] - stats[2 * c] * g;
    float4 v = *(const float4*)(Y + t);
    v.x = fmaxf(v.x * g + bb, 0.0f);
    v.y = fmaxf(v.y * g + bb, 0.0f);
    v.z = fmaxf(v.z * g + bb, 0.0f);
    v.w = fmaxf(v.w * g + bb, 0.0f);
    *(float4*)(out + ((size_t)b * C + c) * N + n) = v;
}

// ---------------------------------------------------------------------------
// host driver
// ---------------------------------------------------------------------------
static inline void run_conv_bn_relu(const float* W, const float* X, float* Y,
                                    float* stats,
                                    const float* gamma, const float* beta,
                                    int M, int Ncols, int K, bool apply_ip) {
    dim3 ggrid(Ncols / 128, M / 128);
    gemm_tf32_kernel<<<ggrid, 256>>>(W, X, Y, M, Ncols, K);
    bn_stats_kernel<<<M, 256>>>(Y, stats, Ncols);
    if (apply_ip) {
        int total = M * Ncols;
        bn_apply_ip_kernel<<<total / 1024, 256>>>(Y, stats, gamma, beta, Ncols);
    }
}

extern "C" void kernel_launch(void* const* d_in, const int* in_sizes, int n_in,
                              void* d_out, int out_size) {
    const float* in[26];
    for (int i = 0; i < 26 && i < n_in; ++i) in[i] = (const float*)d_in[i];

    // Resolve input ordering: interleaved (setup_inputs dict) vs grouped
    // (reference signature). f0 has 4,194,304 elements; xyz1 has 49,152.
    const float *xyz0, *xyz1, *xyz2, *xyz3, *f0, *f1, *f2, *f3;
    if (in_sizes[1] == 8 * 64 * 8192) {  // interleaved: xyz0,f0,xyz1,f1,...
        xyz0 = in[0]; f0 = in[1]; xyz1 = in[2]; f1 = in[3];
        xyz2 = in[4]; f2 = in[5]; xyz3 = in[6]; f3 = in[7];
    } else {  // grouped: xyz0..xyz3, f0..f3
        xyz0 = in[0]; xyz1 = in[1]; xyz2 = in[2]; xyz3 = in[3];
        f0 = in[4]; f1 = in[5]; f2 = in[6]; f3 = in[7];
    }
    const float *w00 = in[8],  *g00 = in[9],  *b00 = in[10];
    const float *w01 = in[11], *g01 = in[12], *b01 = in[13];
    const float *w10 = in[14], *g10 = in[15], *b10 = in[16];
    const float *w11 = in[17], *g11 = in[18], *b11 = in[19];
    const float *w20 = in[20], *g20 = in[21], *b20 = in[22];
    const float *w21 = in[23], *g21 = in[24], *b21 = in[25];

    float *big, *Y00, *mid, *Y20, *F2N, *X1, *F1N, *stats;
    cudaGetSymbolAddress((void**)&big, g_big);
    cudaGetSymbolAddress((void**)&Y00, g_Y00);
    cudaGetSymbolAddress((void**)&mid, g_mid);
    cudaGetSymbolAddress((void**)&Y20, g_Y20);
    cudaGetSymbolAddress((void**)&F2N, g_F2N);
    cudaGetSymbolAddress((void**)&X1, g_X1);
    cudaGetSymbolAddress((void**)&F1N, g_F1N);
    cudaGetSymbolAddress((void**)&stats, g_stats);

    // Aliased views (see buffer comments above):
    float* X2  = mid;   // 768 x 4096 during FP2
    float* Y10 = mid;   // 256 x 16384 during FP1 (X2 dead by then)
    float* X0  = big;   // 192 x 65536 during FP0 concat + conv0
    float* Y01 = big;   // 128 x 65536 after conv0 (X0 dead: conv1 reads Y00)

    float* out = (float*)d_out;
    const int B = B_SZ;

    // ---------------- FP2: xyz2 (n=512) <- xyz3 (m=128) ----------------
    {
        const int n = N2, m = N3, Cskip = 256, Cf = 512, cols = B * n;
        copy_skip_kernel<<<(B * Cskip * n) / 1024, 256>>>(f2, X2, B, Cskip, n);
        knn_interp_kernel<<<dim3(n / 256, B), 256>>>(
            xyz2, xyz3, f3, X2, n, m, Cf, Cskip, /*fb=*/Cf * m, /*fc=*/m, B);
        run_conv_bn_relu(w20, X2, Y20, stats, g20, b20, 256, cols, 768, true);
        run_conv_bn_relu(w21, Y20, F2N, stats, g21, b21, 256, cols, 256, true);
    }

    // ---------------- FP1: xyz1 (n=2048) <- xyz2 (m=512) ----------------
    {
        const int n = N1, m = N2, Cskip = 128, Cf = 256, cols = B * n;
        copy_skip_kernel<<<(B * Cskip * n) / 1024, 256>>>(f1, X1, B, Cskip, n);
        knn_interp_kernel<<<dim3(n / 256, B), 256>>>(
            xyz1, xyz2, F2N, X1, n, m, Cf, Cskip, /*fb=*/m, /*fc=*/B * m, B);
        run_conv_bn_relu(w10, X1, Y10, stats, g10, b10, 256, cols, 384, true);
        run_conv_bn_relu(w11, Y10, F1N, stats, g11, b11, 128, cols, 256, true);
    }

    // ---------------- FP0: xyz0 (n=8192) <- xyz1 (m=2048) ----------------
    {
        const int n = N0, m = N1, Cskip = 64, Cf = 128, cols = B * n;
        copy_skip_kernel<<<(B * Cskip * n) / 1024, 256>>>(f0, X0, B, Cskip, n);
        knn_interp_kernel<<<dim3(n / 256, B), 256>>>(
            xyz0, xyz1, F1N, X0, n, m, Cf, Cskip, /*fb=*/m, /*fc=*/B * m, B);
        run_conv_bn_relu(w00, X0, Y00, stats, g00, b00, 128, cols, 192, true);
        // final conv: stats then apply with transpose into d_out.
        // Y01 aliases X0 (dead after conv0 GEMM read it).
        run_conv_bn_relu(w01, Y00, Y01, stats, g01, b01, 128, cols, 128, false);
        const int total = 128 * cols;
        bn_apply_out_kernel<<<total / 1024, 256>>>(Y01, stats, g01, b01, out,
                                                   B, 128, n);
    }
}